// round 4
// baseline (speedup 1.0000x reference)
#include <cuda_runtime.h>
#include <cstdint>

typedef unsigned long long ull;

// ---------------- problem constants ----------------
#define T_STEPS 2048
#define BATCH   64
#define FEAT    13
#define HID     300
#define OUT_MAIN (BATCH*T_STEPS*FEAT)
#define OUT_EMB_OFF OUT_MAIN

// ---------------- encoder config ----------------
#define CLUSTER 8
#define NB      4               // batch per cluster
#define TENC    480             // 8 ksplit * 60 row-groups
#define HC      38              // hidden units per CTA
#define ROWP    40              // padded rows per gate
#define R3      120
#define KP2     160             // k-pairs per (buffer,batch): 320 floats
#define KSPLIT  8
#define KSEG2   20              // k-pairs per split
#define RG      60              // row-pairs per thread-column
#define XSLOT   152             // pair index where x lives (k=304..316)
#define EXP_BYTES (HID*NB*4)    // 4800 bytes expected per step per CTA

__device__ float g_hlast[BATCH*HID];
__device__ float g_emb[BATCH*HID];

// ---------------- helpers ----------------
__device__ __forceinline__ float sig_f(float x) {
    return __fdividef(1.f, 1.f + __expf(-x));
}
__device__ __forceinline__ float tanh_f(float x) {
    return 1.f - __fdividef(2.f, __expf(2.f * x) + 1.f);
}
__device__ __forceinline__ unsigned smem_u32(const void* p) {
    unsigned a;
    asm("{ .reg .u64 t; cvta.to.shared.u64 t, %1; cvt.u32.u64 %0, t; }"
        : "=r"(a) : "l"(p));
    return a;
}
__device__ __forceinline__ void cluster_sync_() {
    asm volatile("barrier.cluster.arrive.aligned;" ::: "memory");
    asm volatile("barrier.cluster.wait.aligned;" ::: "memory");
}
__device__ __forceinline__ ull pk2(float lo, float hi) {
    ull r;
    asm("mov.b64 %0, {%1, %2};" : "=l"(r) : "f"(lo), "f"(hi));
    return r;
}
__device__ __forceinline__ void fma2(ull& d, ull a, ull b) {
    asm("fma.rn.f32x2 %0, %1, %2, %0;" : "+l"(d) : "l"(a), "l"(b));
}
__device__ __forceinline__ float upks(ull v) {
    float lo, hi;
    asm("mov.b64 {%0, %1}, %2;" : "=f"(lo), "=f"(hi) : "l"(v));
    return lo + hi;
}
__device__ __forceinline__ unsigned mapa_(unsigned a, int rank) {
    unsigned r;
    asm("mapa.shared::cluster.u32 %0, %1, %2;" : "=r"(r) : "r"(a), "r"(rank));
    return r;
}
__device__ __forceinline__ void mbar_init(unsigned a, unsigned cnt) {
    asm volatile("mbarrier.init.shared.b64 [%0], %1;" :: "r"(a), "r"(cnt) : "memory");
}
__device__ __forceinline__ void mbar_expect(unsigned a, unsigned bytes) {
    asm volatile("mbarrier.arrive.expect_tx.shared.b64 _, [%0], %1;"
                 :: "r"(a), "r"(bytes) : "memory");
}
__device__ __forceinline__ void mbar_wait(unsigned a, unsigned par) {
    unsigned done;
    asm volatile(
        "{\n\t.reg .pred p;\n\t"
        "mbarrier.try_wait.parity.acquire.cta.shared::cta.b64 p, [%1], %2;\n\t"
        "selp.b32 %0, 1, 0, p;\n\t}"
        : "=r"(done) : "r"(a), "r"(par) : "memory");
    if (!done) {
        asm volatile(
            "{\n\t.reg .pred P1;\n"
            "WAIT_%=:\n\t"
            "mbarrier.try_wait.parity.acquire.cta.shared::cta.b64 P1, [%0], %1, 0x989680;\n\t"
            "@P1 bra DONE_%=;\n\t"
            "bra WAIT_%=;\n"
            "DONE_%=:\n\t}"
            :: "r"(a), "r"(par) : "memory");
    }
}
__device__ __forceinline__ void st_async_f32(unsigned raddr, float v, unsigned rbar) {
    asm volatile(
        "st.async.shared::cluster.mbarrier::complete_tx::bytes.b32 [%0], %1, [%2];"
        :: "r"(raddr), "f"(v), "r"(rbar) : "memory");
}

// weight fetch with x-fold: k<300 -> Whh, 304<=k<317 && g<2 -> Wih, else 0
__device__ __forceinline__ float wval(const float* __restrict__ Wih,
                                      const float* __restrict__ Whh,
                                      int g, int u, int k) {
    if (k < HID) return Whh[(g * HID + u) * HID + k];
    if (k >= 304 && k < 304 + FEAT && g < 2) return Wih[(g * HID + u) * FEAT + (k - 304)];
    return 0.f;
}

// ======================================================================
// Encoder: 16 clusters x 8 CTAs, 4 batch/cluster. Whh slice in registers
// (f32x2 along k). Per step: pipelined reg GEMM -> coalesced partials ->
// gates -> st.async h broadcast with tx-mbarrier (no cluster barrier).
// ======================================================================
__global__ void __launch_bounds__(TENC, 1) __cluster_dims__(CLUSTER, 1, 1)
enc_kernel(const float* __restrict__ x,
           const float* __restrict__ Wih,
           const float* __restrict__ Whh,
           const float* __restrict__ bih,
           const float* __restrict__ bhh)
{
    __shared__ float2 h2[2][NB][KP2];          // h (+x) pairs, double buffered
    __shared__ float2 part2[NB][KSPLIT][RG];   // partials: coalesced layout
    __shared__ ull    win2[HC * 7];            // n-gate Wih rows (f32x2)
    __shared__ ull    mbars[2];

    const int tid = threadIdx.x;
    unsigned rank;
    asm("mov.u32 %0, %%cluster_ctarank;" : "=r"(rank));
    const int bg = (blockIdx.x / CLUSTER) * NB;

    // ---- zero h2 (both buffers) ----
    {
        float* h2f = (float*)h2;
        for (int i = tid; i < 2 * NB * KP2 * 2; i += TENC) h2f[i] = 0.f;
    }
    // ---- win2: n-gate Wih rows packed ----
    for (int i = tid; i < HC * 7; i += TENC) {
        int r = i / 7, fp = i % 7;
        int u = (int)rank * HC + r;
        float a = 0.f, b = 0.f;
        if (u < HID) {
            a = Wih[(2 * HID + u) * FEAT + 2 * fp];
            if (2 * fp + 1 < FEAT) b = Wih[(2 * HID + u) * FEAT + 2 * fp + 1];
        }
        win2[i] = pk2(a, b);
    }

    // ---- x staging role: threads 152..179 ----
    const int xb_ = (tid - NB * HC) / 7;
    const int xfp = (tid - NB * HC) % 7;
    const bool xok = (tid >= NB * HC) && (tid < NB * HC + NB * 7);
    if (xok) {
        const float* xp = x + ((long)(bg + xb_) * T_STEPS) * FEAT + 2 * xfp;
        float a = xp[0];
        float b = (2 * xfp + 1 < FEAT) ? xp[1] : 0.f;
        h2[0][xb_][XSLOT + xfp] = make_float2(a, b);
    }

    // ---- gemm role: weights into registers ----
    const int ks = tid / RG;          // 0..7
    const int rg = tid % RG;          // 0..59
    const int row0 = rg * 2;
    ull w0[KSEG2], w1[KSEG2];
    {
        int g0 = row0 / ROWP, i0 = row0 % ROWP, u0 = (int)rank * HC + i0;
        bool ok0 = (i0 < HC) && (u0 < HID);
        int g1 = (row0 + 1) / ROWP, i1 = (row0 + 1) % ROWP, u1 = (int)rank * HC + i1;
        bool ok1 = (i1 < HC) && (u1 < HID);
#pragma unroll
        for (int kp = 0; kp < KSEG2; kp++) {
            int k0 = (ks * KSEG2 + kp) * 2;
            float a0 = ok0 ? wval(Wih, Whh, g0, u0, k0) : 0.f;
            float b0 = ok0 ? wval(Wih, Whh, g0, u0, k0 + 1) : 0.f;
            float a1 = ok1 ? wval(Wih, Whh, g1, u1, k0) : 0.f;
            float b1 = ok1 ? wval(Wih, Whh, g1, u1, k0 + 1) : 0.f;
            w0[kp] = pk2(a0, b0);
            w1[kp] = pk2(a1, b1);
        }
    }

    // ---- gate role (tid < 152) ----
    const int gb = tid / HC;
    const int gi_ = tid % HC;
    const int u_g = (int)rank * HC + gi_;
    const bool gate_ok = (tid < NB * HC) && (u_g < HID);
    float brz0 = 0.f, brz1 = 0.f, bin_ = 0.f, bhn_ = 0.f, h_keep = 0.f;
    if (gate_ok) {
        brz0 = bih[u_g]           + bhh[u_g];
        brz1 = bih[HID + u_g]     + bhh[HID + u_g];
        bin_ = bih[2 * HID + u_g];
        bhn_ = bhh[2 * HID + u_g];
    }

    // ---- mbarrier init ----
    const unsigned barb = smem_u32(mbars);
    const unsigned h_base = smem_u32(h2);
    if (tid == 0) {
        mbar_init(barb, 1);
        mbar_init(barb + 8, 1);
        mbar_expect(barb, EXP_BYTES);
        mbar_expect(barb + 8, EXP_BYTES);
    }
    __syncthreads();
    cluster_sync_();   // all CTAs: smem init + mbarriers visible cluster-wide

    for (int t = 0; t < T_STEPS; t++) {
        const int p = t & 1;

        if (t) {
            const unsigned bw = barb + (unsigned)((t - 1) & 1) * 8u;
            mbar_wait(bw, (unsigned)(((t - 1) >> 1) & 1));
            if (tid == 0) mbar_expect(bw, EXP_BYTES);
        }

        // x prefetch for t+1 (hidden under gemm)
        float xa = 0.f, xbv = 0.f;
        if (xok && t + 1 < T_STEPS) {
            const float* xp = x + ((long)(bg + xb_) * T_STEPS + (t + 1)) * FEAT + 2 * xfp;
            xa = __ldg(xp);
            xbv = (2 * xfp + 1 < FEAT) ? __ldg(xp + 1) : 0.f;
        }

        // ---- GEMM (software pipelined h loads) ----
        {
            ull a00 = 0, a01 = 0, a10 = 0, a11 = 0;
            ull a20 = 0, a21 = 0, a30 = 0, a31 = 0;
            const ull* hp = (const ull*)h2 + (size_t)p * NB * KP2 + ks * KSEG2;
            ull hv0 = hp[0], hv1 = hp[KP2], hv2 = hp[2 * KP2], hv3 = hp[3 * KP2];
#pragma unroll
            for (int kp = 0; kp < KSEG2; kp++) {
                ull c0 = hv0, c1 = hv1, c2 = hv2, c3 = hv3;
                if (kp + 1 < KSEG2) {
                    hv0 = hp[kp + 1];
                    hv1 = hp[kp + 1 + KP2];
                    hv2 = hp[kp + 1 + 2 * KP2];
                    hv3 = hp[kp + 1 + 3 * KP2];
                }
                fma2(a00, w0[kp], c0); fma2(a01, w1[kp], c0);
                fma2(a10, w0[kp], c1); fma2(a11, w1[kp], c1);
                fma2(a20, w0[kp], c2); fma2(a21, w1[kp], c2);
                fma2(a30, w0[kp], c3); fma2(a31, w1[kp], c3);
            }
            part2[0][ks][rg] = make_float2(upks(a00), upks(a01));
            part2[1][ks][rg] = make_float2(upks(a10), upks(a11));
            part2[2][ks][rg] = make_float2(upks(a20), upks(a21));
            part2[3][ks][rg] = make_float2(upks(a30), upks(a31));
        }
        if (xok && t + 1 < T_STEPS)
            h2[p ^ 1][xb_][XSLOT + xfp] = make_float2(xa, xbv);

        __syncthreads();

        if (gate_ok) {
            // partial reduction: part2 viewed as float[b][ks][120]
            const float* pf = (const float*)part2;
            float s0 = 0.f, s1 = 0.f, s2 = 0.f;
#pragma unroll
            for (int q = 0; q < KSPLIT; q++) {
                const int base = (gb * KSPLIT + q) * R3;
                s0 += pf[base + gi_];
                s1 += pf[base + ROWP + gi_];
                s2 += pf[base + 2 * ROWP + gi_];
            }
            // n-gate input dot from x slots
            ull in2 = 0;
            const ull* xq = (const ull*)&h2[p][gb][XSLOT];
#pragma unroll
            for (int fp = 0; fp < 7; fp++) fma2(in2, win2[gi_ * 7 + fp], xq[fp]);
            const float i_n = upks(in2);

            const float r = sig_f(s0 + brz0);
            const float z = sig_f(s1 + brz1);
            const float n = tanh_f(i_n + bin_ + r * (s2 + bhn_));
            const float hn = (1.f - z) * n + z * h_keep;
            h_keep = hn;

            if (t + 1 < T_STEPS) {
                const unsigned dst = h_base
                    + ((unsigned)(((p ^ 1) * NB + gb) * KP2)) * 8u + (unsigned)u_g * 4u;
                const unsigned bl = barb + (unsigned)(t & 1) * 8u;
#pragma unroll
                for (int c = 0; c < CLUSTER; c++)
                    st_async_f32(mapa_(dst, c), hn, mapa_(bl, c));
            }
        }
        // no trailing barrier: next iteration's mbar_wait provides ordering
    }

    if (gate_ok) g_hlast[(bg + gb) * HID + u_g] = h_keep;
}

// ======================================================================
// fc + relu
// ======================================================================
__global__ void __launch_bounds__(128) fc_kernel(
    const float* __restrict__ fcW, const float* __restrict__ fcb,
    float* __restrict__ dout, int write_emb)
{
    __shared__ float hs[HID];
    const int b = blockIdx.x;
    const int tid = threadIdx.x;
    for (int k = tid; k < HID; k += 128) hs[k] = g_hlast[b * HID + k];
    __syncthreads();
    for (int j = tid; j < HID; j += 128) {
        float a = fcb[j];
        const float* w = fcW + j * HID;
#pragma unroll 4
        for (int k = 0; k < HID; k++) a = fmaf(w[k], hs[k], a);
        a = fmaxf(a, 0.f);
        g_emb[b * HID + j] = a;
        if (write_emb) dout[OUT_EMB_OFF + b * HID + j] = a;
    }
}

// ======================================================================
// Decoder: one warp per batch element, h broadcast via shfl.
// ======================================================================
__global__ void __launch_bounds__(32) dec_kernel(
    const float* __restrict__ dWih, const float* __restrict__ dWhh,
    const float* __restrict__ dbih, const float* __restrict__ dbhh,
    float* __restrict__ out)
{
    const int b = blockIdx.x;
    const int lane = threadIdx.x;

    float wr[FEAT], wz[FEAT], wn[FEAT];
    float gr0 = 0.f, gz0 = 0.f, gn0 = 0.f, bhn = 0.f, h = 0.f;

    if (lane < FEAT) {
        gr0 = dbih[lane]            + dbhh[lane];
        gz0 = dbih[FEAT + lane]     + dbhh[FEAT + lane];
        gn0 = dbih[2 * FEAT + lane];
        bhn = dbhh[2 * FEAT + lane];
        const float* e  = g_emb + b * HID;
        const float* w0 = dWih + lane * HID;
        const float* w1 = dWih + (FEAT + lane) * HID;
        const float* w2 = dWih + (2 * FEAT + lane) * HID;
#pragma unroll 4
        for (int k = 0; k < HID; k++) {
            float ev = e[k];
            gr0 = fmaf(w0[k], ev, gr0);
            gz0 = fmaf(w1[k], ev, gz0);
            gn0 = fmaf(w2[k], ev, gn0);
        }
#pragma unroll
        for (int k = 0; k < FEAT; k++) {
            wr[k] = dWhh[lane * FEAT + k];
            wz[k] = dWhh[(FEAT + lane) * FEAT + k];
            wn[k] = dWhh[(2 * FEAT + lane) * FEAT + k];
        }
    }

    float* ob = out + (long)b * T_STEPS * FEAT;
    for (int t = 0; t < T_STEPS; t++) {
        float sr = 0.f, sz = 0.f, sn = 0.f;
#pragma unroll
        for (int k = 0; k < FEAT; k++) {
            float hk = __shfl_sync(0xffffffffu, h, k);
            sr = fmaf(wr[k], hk, sr);
            sz = fmaf(wz[k], hk, sz);
            sn = fmaf(wn[k], hk, sn);
        }
        if (lane < FEAT) {
            float r = sig_f(gr0 + sr);
            float z = sig_f(gz0 + sz);
            float n = tanh_f(gn0 + r * (sn + bhn));
            h = (1.f - z) * n + z * h;
            ob[t * FEAT + lane] = h;
        }
    }
}

// ======================================================================
// launch
// ======================================================================
extern "C" void kernel_launch(void* const* d_in, const int* in_sizes, int n_in,
                              void* d_out, int out_size)
{
    const float* x        = (const float*)d_in[0];
    const float* enc_Wih  = (const float*)d_in[1];
    const float* enc_Whh  = (const float*)d_in[2];
    const float* enc_bih  = (const float*)d_in[3];
    const float* enc_bhh  = (const float*)d_in[4];
    const float* fc_W     = (const float*)d_in[5];
    const float* fc_b     = (const float*)d_in[6];
    const float* dec_Wih  = (const float*)d_in[7];
    const float* dec_Whh  = (const float*)d_in[8];
    const float* dec_bih  = (const float*)d_in[9];
    const float* dec_bhh  = (const float*)d_in[10];
    float* out = (float*)d_out;

    const int write_emb = (out_size >= OUT_MAIN + BATCH * HID) ? 1 : 0;

    enc_kernel<<<(BATCH / NB) * CLUSTER, TENC>>>(
        x, enc_Wih, enc_Whh, enc_bih, enc_bhh);
    fc_kernel<<<BATCH, 128>>>(fc_W, fc_b, out, write_emb);
    dec_kernel<<<BATCH, 32>>>(dec_Wih, dec_Whh, dec_bih, dec_bhh, out);
}

// round 5
// speedup vs baseline: 1.3819x; 1.3819x over previous
#include <cuda_runtime.h>
#include <cstdint>

typedef unsigned long long ull;

// ---------------- problem constants ----------------
#define T_STEPS 2048
#define BATCH   64
#define FEAT    13
#define HID     300
#define OUT_MAIN (BATCH*T_STEPS*FEAT)
#define OUT_EMB_OFF OUT_MAIN

// ---------------- encoder config ----------------
#define CLUSTER 8
#define NB      4               // batch per cluster
#define TENC    480
#define HC      38              // hidden units per CTA (8*38 = 304 >= 300)
#define ROWP    40              // padded rows per gate
#define R3      120
#define KSPLIT  8               // one k-split per source rank chunk
#define KSEG2   19              // k-pairs per rank chunk (38 floats)
#define RG      60              // row-pairs; 8*60 = 480 threads
#define CHUNK_BYTES (NB*KSEG2*8)        // 608 B per CTA per step
#define EXP_BYTES   (CLUSTER*CHUNK_BYTES) // 4864 B expected per step per CTA

__device__ float g_hlast[BATCH*HID];
__device__ float g_emb[BATCH*HID];

// ---------------- helpers ----------------
__device__ __forceinline__ float sig_f(float x) {
    return __fdividef(1.f, 1.f + __expf(-x));
}
__device__ __forceinline__ float tanh_f(float x) {
    return 1.f - __fdividef(2.f, __expf(2.f * x) + 1.f);
}
__device__ __forceinline__ unsigned smem_u32(const void* p) {
    unsigned a;
    asm("{ .reg .u64 t; cvta.to.shared.u64 t, %1; cvt.u32.u64 %0, t; }"
        : "=r"(a) : "l"(p));
    return a;
}
__device__ __forceinline__ void cluster_sync_() {
    asm volatile("barrier.cluster.arrive.aligned;" ::: "memory");
    asm volatile("barrier.cluster.wait.aligned;" ::: "memory");
}
__device__ __forceinline__ ull pk2(float lo, float hi) {
    ull r;
    asm("mov.b64 %0, {%1, %2};" : "=l"(r) : "f"(lo), "f"(hi));
    return r;
}
__device__ __forceinline__ void fma2(ull& d, ull a, ull b) {
    asm("fma.rn.f32x2 %0, %1, %2, %0;" : "+l"(d) : "l"(a), "l"(b));
}
__device__ __forceinline__ float upks(ull v) {
    float lo, hi;
    asm("mov.b64 {%0, %1}, %2;" : "=f"(lo), "=f"(hi) : "l"(v));
    return lo + hi;
}
__device__ __forceinline__ unsigned mapa_(unsigned a, int rank) {
    unsigned r;
    asm("mapa.shared::cluster.u32 %0, %1, %2;" : "=r"(r) : "r"(a), "r"(rank));
    return r;
}
__device__ __forceinline__ void mbar_init(unsigned a, unsigned cnt) {
    asm volatile("mbarrier.init.shared.b64 [%0], %1;" :: "r"(a), "r"(cnt) : "memory");
}
__device__ __forceinline__ void mbar_expect(unsigned a, unsigned bytes) {
    asm volatile("mbarrier.arrive.expect_tx.shared.b64 _, [%0], %1;"
                 :: "r"(a), "r"(bytes) : "memory");
}
__device__ __forceinline__ void mbar_wait(unsigned a, unsigned par) {
    unsigned done;
    asm volatile(
        "{\n\t.reg .pred p;\n\t"
        "mbarrier.try_wait.parity.acquire.cta.shared::cta.b64 p, [%1], %2;\n\t"
        "selp.b32 %0, 1, 0, p;\n\t}"
        : "=r"(done) : "r"(a), "r"(par) : "memory");
    if (!done) {
        asm volatile(
            "{\n\t.reg .pred P1;\n"
            "WAIT_%=:\n\t"
            "mbarrier.try_wait.parity.acquire.cta.shared::cta.b64 P1, [%0], %1, 0x989680;\n\t"
            "@P1 bra DONE_%=;\n\t"
            "bra WAIT_%=;\n"
            "DONE_%=:\n\t}"
            :: "r"(a), "r"(par) : "memory");
    }
}
// SMEM(cta) -> SMEM(cluster) bulk copy, completes on remote mbarrier (one tx update)
__device__ __forceinline__ void bulk_copy_cluster(unsigned dst_cluster, unsigned src_cta,
                                                  unsigned bytes, unsigned remote_mbar) {
    asm volatile(
        "cp.async.bulk.shared::cluster.shared::cta.mbarrier::complete_tx::bytes "
        "[%0], [%1], %2, [%3];"
        :: "r"(dst_cluster), "r"(src_cta), "r"(bytes), "r"(remote_mbar) : "memory");
}
__device__ __forceinline__ void fence_async_() {
    asm volatile("fence.proxy.async.shared::cta;" ::: "memory");
}

// ======================================================================
// Encoder: 16 clusters x 8 CTAs, 4 batch/cluster. Whh slice in registers
// (f32x2 along k). h lives rank-chunked: hbuf[buf][rank][batch][19 pairs],
// broadcast per step = ONE cp.async.bulk (608B) per destination CTA.
// ======================================================================
__global__ void __launch_bounds__(TENC, 1) __cluster_dims__(CLUSTER, 1, 1)
enc_kernel(const float* __restrict__ x,
           const float* __restrict__ Wih,
           const float* __restrict__ Whh,
           const float* __restrict__ bih,
           const float* __restrict__ bhh)
{
    __shared__ __align__(16) float2 hbuf[2][CLUSTER][NB][KSEG2]; // 9728 B
    __shared__ float2 part2[NB][KSPLIT][RG];                     // 15360 B
    __shared__ float2 xst[2][NB][7];                             // 448 B
    __shared__ ull    mbars[2];

    const int tid = threadIdx.x;
    unsigned rank;
    asm("mov.u32 %0, %%cluster_ctarank;" : "=r"(rank));
    const int bg = (blockIdx.x / CLUSTER) * NB;

    // ---- zero h buffers ----
    {
        float* hf = (float*)hbuf;
        for (int i = tid; i < 2 * CLUSTER * NB * KSEG2 * 2; i += TENC) hf[i] = 0.f;
    }

    // ---- gemm role: weights into registers (k-order = rank-chunk order = identity) ----
    const int ks = tid / RG;          // 0..7  (rank chunk)
    const int rg = tid % RG;          // 0..59
    const int row0 = rg * 2;
    ull w0[KSEG2], w1[KSEG2];
    {
        int g0 = row0 / ROWP, i0 = row0 % ROWP, u0 = (int)rank * HC + i0;
        bool ok0 = (i0 < HC) && (u0 < HID);
        int g1 = (row0 + 1) / ROWP, i1 = (row0 + 1) % ROWP, u1 = (int)rank * HC + i1;
        bool ok1 = (i1 < HC) && (u1 < HID);
#pragma unroll
        for (int kp = 0; kp < KSEG2; kp++) {
            int k0 = ks * (2 * KSEG2) + kp * 2;   // global k of pair
            float a0 = (ok0 && k0     < HID) ? Whh[(g0 * HID + u0) * HID + k0]     : 0.f;
            float b0 = (ok0 && k0 + 1 < HID) ? Whh[(g0 * HID + u0) * HID + k0 + 1] : 0.f;
            float a1 = (ok1 && k0     < HID) ? Whh[(g1 * HID + u1) * HID + k0]     : 0.f;
            float b1 = (ok1 && k0 + 1 < HID) ? Whh[(g1 * HID + u1) * HID + k0 + 1] : 0.f;
            w0[kp] = pk2(a0, b0);
            w1[kp] = pk2(a1, b1);
        }
    }

    // ---- gate role (tid < 152): all 3 input-gate Wih rows in registers ----
    const int gb = tid / HC;
    const int gi_ = tid % HC;
    const int u_g = (int)rank * HC + gi_;
    const bool gate_ok = (tid < NB * HC) && (u_g < HID);
    ull wih[3][7];
    float brz0 = 0.f, brz1 = 0.f, bin_ = 0.f, bhn_ = 0.f, h_keep = 0.f;
    if (gate_ok) {
#pragma unroll
        for (int g = 0; g < 3; g++)
#pragma unroll
            for (int fp = 0; fp < 7; fp++) {
                float a = Wih[(g * HID + u_g) * FEAT + 2 * fp];
                float b = (2 * fp + 1 < FEAT) ? Wih[(g * HID + u_g) * FEAT + 2 * fp + 1] : 0.f;
                wih[g][fp] = pk2(a, b);
            }
        brz0 = bih[u_g]           + bhh[u_g];
        brz1 = bih[HID + u_g]     + bhh[HID + u_g];
        bin_ = bih[2 * HID + u_g];
        bhn_ = bhh[2 * HID + u_g];
    }

    // ---- x staging role: threads 152..179 ----
    const int xb_ = (tid - NB * HC) / 7;
    const int xfp = (tid - NB * HC) % 7;
    const bool xok = (tid >= NB * HC) && (tid < NB * HC + NB * 7);
    if (xok) {
        const float* xp = x + ((long)(bg + xb_) * T_STEPS) * FEAT + 2 * xfp;
        float a = xp[0];
        float b = (2 * xfp + 1 < FEAT) ? xp[1] : 0.f;
        xst[0][xb_][xfp] = make_float2(a, b);
    }

    // ---- mbarrier init + cluster-wide visibility ----
    const unsigned barb = smem_u32(mbars);
    const unsigned hbase = smem_u32(hbuf);
    if (tid == 0) {
        mbar_init(barb, 1);
        mbar_init(barb + 8, 1);
        mbar_expect(barb, EXP_BYTES);
        mbar_expect(barb + 8, EXP_BYTES);
    }
    __syncthreads();
    cluster_sync_();

    for (int t = 0; t < T_STEPS; t++) {
        const int p = t & 1;

        if (t) {
            const unsigned bw = barb + (unsigned)((t - 1) & 1) * 8u;
            mbar_wait(bw, (unsigned)(((t - 1) >> 1) & 1));
            if (tid == 0) mbar_expect(bw, EXP_BYTES);
        }

        // x prefetch for t+1 (independent; hides under GEMM)
        if (xok && t + 1 < T_STEPS) {
            const float* xp = x + ((long)(bg + xb_) * T_STEPS + (t + 1)) * FEAT + 2 * xfp;
            float a = __ldg(xp);
            float b = (2 * xfp + 1 < FEAT) ? __ldg(xp + 1) : 0.f;
            xst[p ^ 1][xb_][xfp] = make_float2(a, b);
        }

        // ---- GEMM over this rank-chunk's k (19 pairs), 4 batch x 2 rows ----
        {
            ull a00 = 0, a01 = 0, a10 = 0, a11 = 0;
            ull a20 = 0, a21 = 0, a30 = 0, a31 = 0;
            const ull* hp = (const ull*)hbuf + ((size_t)p * CLUSTER + ks) * NB * KSEG2;
            ull hv0 = hp[0], hv1 = hp[KSEG2], hv2 = hp[2 * KSEG2], hv3 = hp[3 * KSEG2];
#pragma unroll
            for (int kp = 0; kp < KSEG2; kp++) {
                ull c0 = hv0, c1 = hv1, c2 = hv2, c3 = hv3;
                if (kp + 1 < KSEG2) {
                    hv0 = hp[kp + 1];
                    hv1 = hp[kp + 1 + KSEG2];
                    hv2 = hp[kp + 1 + 2 * KSEG2];
                    hv3 = hp[kp + 1 + 3 * KSEG2];
                }
                fma2(a00, w0[kp], c0); fma2(a01, w1[kp], c0);
                fma2(a10, w0[kp], c1); fma2(a11, w1[kp], c1);
                fma2(a20, w0[kp], c2); fma2(a21, w1[kp], c2);
                fma2(a30, w0[kp], c3); fma2(a31, w1[kp], c3);
            }
            part2[0][ks][rg] = make_float2(upks(a00), upks(a01));
            part2[1][ks][rg] = make_float2(upks(a10), upks(a11));
            part2[2][ks][rg] = make_float2(upks(a20), upks(a21));
            part2[3][ks][rg] = make_float2(upks(a30), upks(a31));
        }

        __syncthreads();

        if (gate_ok) {
            const float* pf = (const float*)part2;
            float s0 = 0.f, s1 = 0.f, s2 = 0.f;
#pragma unroll
            for (int q = 0; q < KSPLIT; q++) {
                const int base = (gb * KSPLIT + q) * R3;
                s0 += pf[base + gi_];
                s1 += pf[base + ROWP + gi_];
                s2 += pf[base + 2 * ROWP + gi_];
            }
            // input-gate dots from staged x
            ull d0 = 0, d1 = 0, d2 = 0;
            const ull* xq = (const ull*)&xst[p][gb][0];
#pragma unroll
            for (int fp = 0; fp < 7; fp++) {
                ull xv = xq[fp];
                fma2(d0, wih[0][fp], xv);
                fma2(d1, wih[1][fp], xv);
                fma2(d2, wih[2][fp], xv);
            }
            const float r = sig_f(upks(d0) + s0 + brz0);
            const float z = sig_f(upks(d1) + s1 + brz1);
            const float n = tanh_f(upks(d2) + bin_ + r * (s2 + bhn_));
            const float hn = (1.f - z) * n + z * h_keep;
            h_keep = hn;
            // local write of our chunk (float view of hbuf)
            ((float*)hbuf)[((((p ^ 1) * CLUSTER + (int)rank) * NB) + gb) * (2 * KSEG2) + gi_] = hn;
            fence_async_();
        }

        __syncthreads();

        // one bulk copy per destination CTA (threads 0..7), single tx each
        if (t + 1 < T_STEPS && tid < CLUSTER) {
            const unsigned off = (unsigned)(((p ^ 1) * CLUSTER + (int)rank) * CHUNK_BYTES);
            const unsigned src = hbase + off;
            const unsigned bl = barb + (unsigned)(t & 1) * 8u;
            bulk_copy_cluster(mapa_(src, tid), src, CHUNK_BYTES, mapa_(bl, tid));
        }
    }

    if (gate_ok) g_hlast[(bg + gb) * HID + u_g] = h_keep;
}

// ======================================================================
// fc + relu
// ======================================================================
__global__ void __launch_bounds__(128) fc_kernel(
    const float* __restrict__ fcW, const float* __restrict__ fcb,
    float* __restrict__ dout, int write_emb)
{
    __shared__ float hs[HID];
    const int b = blockIdx.x;
    const int tid = threadIdx.x;
    for (int k = tid; k < HID; k += 128) hs[k] = g_hlast[b * HID + k];
    __syncthreads();
    for (int j = tid; j < HID; j += 128) {
        float a = fcb[j];
        const float* w = fcW + j * HID;
#pragma unroll 4
        for (int k = 0; k < HID; k++) a = fmaf(w[k], hs[k], a);
        a = fmaxf(a, 0.f);
        g_emb[b * HID + j] = a;
        if (write_emb) dout[OUT_EMB_OFF + b * HID + j] = a;
    }
}

// ======================================================================
// Decoder: one warp per batch element, h broadcast via shfl.
// ======================================================================
__global__ void __launch_bounds__(32) dec_kernel(
    const float* __restrict__ dWih, const float* __restrict__ dWhh,
    const float* __restrict__ dbih, const float* __restrict__ dbhh,
    float* __restrict__ out)
{
    const int b = blockIdx.x;
    const int lane = threadIdx.x;

    float wr[FEAT], wz[FEAT], wn[FEAT];
    float gr0 = 0.f, gz0 = 0.f, gn0 = 0.f, bhn = 0.f, h = 0.f;

    if (lane < FEAT) {
        gr0 = dbih[lane]            + dbhh[lane];
        gz0 = dbih[FEAT + lane]     + dbhh[FEAT + lane];
        gn0 = dbih[2 * FEAT + lane];
        bhn = dbhh[2 * FEAT + lane];
        const float* e  = g_emb + b * HID;
        const float* w0 = dWih + lane * HID;
        const float* w1 = dWih + (FEAT + lane) * HID;
        const float* w2 = dWih + (2 * FEAT + lane) * HID;
#pragma unroll 4
        for (int k = 0; k < HID; k++) {
            float ev = e[k];
            gr0 = fmaf(w0[k], ev, gr0);
            gz0 = fmaf(w1[k], ev, gz0);
            gn0 = fmaf(w2[k], ev, gn0);
        }
#pragma unroll
        for (int k = 0; k < FEAT; k++) {
            wr[k] = dWhh[lane * FEAT + k];
            wz[k] = dWhh[(FEAT + lane) * FEAT + k];
            wn[k] = dWhh[(2 * FEAT + lane) * FEAT + k];
        }
    }

    float* ob = out + (long)b * T_STEPS * FEAT;
    for (int t = 0; t < T_STEPS; t++) {
        float sr = 0.f, sz = 0.f, sn = 0.f;
#pragma unroll
        for (int k = 0; k < FEAT; k++) {
            float hk = __shfl_sync(0xffffffffu, h, k);
            sr = fmaf(wr[k], hk, sr);
            sz = fmaf(wz[k], hk, sz);
            sn = fmaf(wn[k], hk, sn);
        }
        if (lane < FEAT) {
            float r = sig_f(gr0 + sr);
            float z = sig_f(gz0 + sz);
            float n = tanh_f(gn0 + r * (sn + bhn));
            h = (1.f - z) * n + z * h;
            ob[t * FEAT + lane] = h;
        }
    }
}

// ======================================================================
// launch
// ======================================================================
extern "C" void kernel_launch(void* const* d_in, const int* in_sizes, int n_in,
                              void* d_out, int out_size)
{
    const float* x        = (const float*)d_in[0];
    const float* enc_Wih  = (const float*)d_in[1];
    const float* enc_Whh  = (const float*)d_in[2];
    const float* enc_bih  = (const float*)d_in[3];
    const float* enc_bhh  = (const float*)d_in[4];
    const float* fc_W     = (const float*)d_in[5];
    const float* fc_b     = (const float*)d_in[6];
    const float* dec_Wih  = (const float*)d_in[7];
    const float* dec_Whh  = (const float*)d_in[8];
    const float* dec_bih  = (const float*)d_in[9];
    const float* dec_bhh  = (const float*)d_in[10];
    float* out = (float*)d_out;

    const int write_emb = (out_size >= OUT_MAIN + BATCH * HID) ? 1 : 0;

    enc_kernel<<<(BATCH / NB) * CLUSTER, TENC>>>(
        x, enc_Wih, enc_Whh, enc_bih, enc_bhh);
    fc_kernel<<<BATCH, 128>>>(fc_W, fc_b, out, write_emb);
    dec_kernel<<<BATCH, 32>>>(dec_Wih, dec_Whh, dec_bih, dec_bhh, out);
}